// round 14
// baseline (speedup 1.0000x reference)
#include <cuda_runtime.h>
#include <cuda_fp16.h>
#include <cstdint>

// ---------------------------------------------------------------------------
// SpinConvSq2dSparse: N=8, Lx=Ly=128, C=16, K=9 (-> 5 effective taps), F_IN=64
// Round 14: output tile 8x16, ONE warp per output row, all 6 n-tiles in-lane.
//   - halves LDSM (no par-pair duplication), halo ratio 1.41 (tile 10x18)
//   - register epilogue now covers both d-halves per lane (h = 0,1)
//   - acc 88 regs -> 2 CTAs/SM; B fragments loaded per-nt (2 regs live)
// ---------------------------------------------------------------------------

#define TPH   72     // f16 per tile pixel row (144B; ldmatrix conflict-free)
#define TROW  18     // tile pixels per x-row
#define NROW  10     // tile x-rows (8 + halo 2)
#define NTP   (NROW * TROW)                       // 180 tile pixels
#define NWFRAG 3840  // 2 arrays x 5 taps x 6 nt x 2 regs x 32 lanes (u32)
#define SMEM_BYTES (NTP * TPH * 2 + 384 * 4)      // 25920 + 1536 = 27456 B

__device__ uint32_t g_Bfrag[NWFRAG];

// ---- mma helpers (sm_100a) ----
__device__ __forceinline__ void ldsm_x4(uint32_t* r, uint32_t addr) {
    asm volatile("ldmatrix.sync.aligned.m8n8.x4.shared.b16 {%0,%1,%2,%3}, [%4];"
                 : "=r"(r[0]), "=r"(r[1]), "=r"(r[2]), "=r"(r[3]) : "r"(addr));
}
__device__ __forceinline__ void mma_f16(float* c, const uint32_t* a, const uint32_t* b) {
    asm volatile("mma.sync.aligned.m16n8k16.row.col.f32.f16.f16.f32 "
                 "{%0,%1,%2,%3}, {%4,%5,%6,%7}, {%8,%9}, {%0,%1,%2,%3};"
                 : "+f"(c[0]), "+f"(c[1]), "+f"(c[2]), "+f"(c[3])
                 : "r"(a[0]), "r"(a[1]), "r"(a[2]), "r"(a[3]),
                   "r"(b[0]), "r"(b[1]));
}

// ---------------------------------------------------------------------------
// Effective weight (prefactors folded). tap0 = sum k=0..4 (center);
// tap1..4 = k=5..8 -> (x-1),(x+1),(y-1),(y+1).
// cols n: [0:16)=s110/a0-class, [16:32)=s101/b-class, [32:48)=t-class
// ---------------------------------------------------------------------------
__device__ __forceinline__ float effw(int isB, int tap, int c, int n,
                                      const float* w000, const float* w011,
                                      const float* w101, const float* w110,
                                      const float* w111) {
    const double C0  = 0.28209479177387814;
    const double C1  = 0.4886025119029199;
    const double IS3 = 0.57735026918962576;
    const double IS6 = 0.40824829046386302;
    const double PW0 = 0.058925565098878960;   // sqrt(1/(9*2*16))
    const double PW1 = 1.0 / 12.0;             // sqrt(3/(9*3*16))
    int cls = n >> 4, d = n & 15;
    int off = c * 16 + d;
    const float* w;
    double pf;
    if (!isB) {
        if (cls == 0)      { w = w110; pf = PW0 * IS3 * C1; }
        else if (cls == 1) { w = w101; pf = PW1 * C0 * IS3; }
        else               { w = w111; pf = PW1 * IS6 * C1; }
    } else {
        if (cls == 0)      { w = w000; pf = PW0 * C0; }
        else if (cls == 1) { w = w011; pf = PW1 * IS3 * C1; }
        else               return 0.f;
    }
    float s;
    if (tap == 0) {
        s = 0.f;
        #pragma unroll
        for (int k = 0; k < 5; k++) s += w[k * 256 + off];
    } else {
        s = w[(tap + 4) * 256 + off];
    }
    return (float)(pf * (double)s);
}

// Prep: emit B fragments in HMMA per-lane layout, packed f16x2.
// idx = arr*1920 + tap*384 + nt*64 + r*32 + lane
__global__ void prep_weights(const float* __restrict__ w000,
                             const float* __restrict__ w011,
                             const float* __restrict__ w101,
                             const float* __restrict__ w110,
                             const float* __restrict__ w111) {
    int idx = blockIdx.x * blockDim.x + threadIdx.x;
    if (idx >= NWFRAG) return;
    int l   = idx & 31;
    int r   = (idx >> 5) & 1;
    int nt  = (idx >> 6) % 6;
    int tap = ((idx >> 6) / 6) % 5;
    int arr = idx / 1920;
    int n  = 8 * nt + (l >> 2);
    int c0 = 2 * (l & 3) + 8 * r;
    float v0 = effw(arr, tap, c0,     n, w000, w011, w101, w110, w111);
    float v1 = effw(arr, tap, c0 + 1, n, w000, w011, w101, w110, w111);
    __half2 h = __floats2half2_rn(v0, v1);
    g_Bfrag[idx] = *(uint32_t*)&h;
}

// ---------------------------------------------------------------------------
// Main kernel: one CTA per (n, xb, yb): output tile 8 x-rows x 16 y-cols.
// 256 threads (8 warps). Warp w = output row; all 6 n-tiles in-lane.
// ---------------------------------------------------------------------------
__global__ __launch_bounds__(256, 2)
void spinconv_kernel(const float* __restrict__ feat,
                     const float* __restrict__ spin,
                     float* __restrict__ out) {
    extern __shared__ float smem[];
    __half* tileH = (__half*)smem;              // f16 feat tile (180 x 72)
    float*  sSpin = smem + (NTP * TPH) / 2;     // 384 floats (8 rows x 48)

    const int b   = blockIdx.x;
    const int n   = b >> 7;
    const int xb  = (b >> 3) & 15;   // 16 blocks of 8 x-rows
    const int yb  = b & 7;           // 8 blocks of 16 y-cols
    const int tid = threadIdx.x;

    // ---- stage spin block (8 x 16 px x 3) coalesced ----
    if (tid < 96) {
        int r = tid / 12, i = tid - r * 12;
        size_t q0 = ((size_t)n * 128 + xb * 8 + r) * 128 + yb * 16;
        float4 v = *(const float4*)(spin + q0 * 3 + i * 4);
        *(float4*)(sSpin + r * 48 + i * 4) = v;
    }

    // ---- load feat tile (180 px = 10 rows x 18 cols, circular halo),
    //      de-interleave to f16 planes [x0 | x1_i0 | x1_i1 | x1_i2]. ----
    const size_t nbase = (size_t)n * (128 * 128 * 64);
    for (int idx = tid; idx < NTP * 6; idx += 256) {
        int tp = idx / 6;
        int s  = idx - tp * 6;
        int tr = tp / TROW;
        int tc = tp - tr * TROW;
        int gx = (xb * 8 + tr + 127) & 127;
        int gy = (yb * 16 + tc + 127) & 127;
        const float* src = feat + nbase + ((size_t)gx * 128 + gy) * 64;
        __half* dst = tileH + tp * TPH;
        if (s < 2) {                           // x0 plane: 8 floats -> STS.128
            const float* u = src + 8 * s;
            float4 v0 = *(const float4*)(u);
            float4 v1 = *(const float4*)(u + 4);
            __half2 h0 = __floats2half2_rn(v0.x, v0.y);
            __half2 h1 = __floats2half2_rn(v0.z, v0.w);
            __half2 h2 = __floats2half2_rn(v1.x, v1.y);
            __half2 h3 = __floats2half2_rn(v1.z, v1.w);
            uint4 pk = make_uint4(*(uint32_t*)&h0, *(uint32_t*)&h1,
                                  *(uint32_t*)&h2, *(uint32_t*)&h3);
            *(uint4*)(dst + 8 * s) = pk;
        } else {                               // x1 chunk: channels 4j..4j+3
            int j = s - 2;
            const float* u = src + 16 + 12 * j;
            float4 A = *(const float4*)(u);
            float4 B = *(const float4*)(u + 4);
            float4 C = *(const float4*)(u + 8);
            float f[12] = {A.x, A.y, A.z, A.w, B.x, B.y, B.z, B.w,
                           C.x, C.y, C.z, C.w};
            #pragma unroll
            for (int i = 0; i < 3; i++) {      // plane i
                __half2 lo = __floats2half2_rn(f[i],     f[3 + i]);
                __half2 hi = __floats2half2_rn(f[6 + i], f[9 + i]);
                uint2 pk;
                pk.x = *(uint32_t*)&lo;
                pk.y = *(uint32_t*)&hi;
                *(uint2*)(dst + (1 + i) * 16 + 4 * j) = pk;
            }
        }
    }
    __syncthreads();

    // ---- tensor-core GEMM: warp pb = output row; acc[g][nt][4] ----
    const int pb   = tid >> 5;                // output row 0..7
    const int lane = tid & 31;
    const int laneRow = lane & 15;
    const int cOffB   = (lane & 16) ? 16 : 0; // k-half byte offset
    const uint32_t tbase = (uint32_t)__cvta_generic_to_shared(tileH);
    const int rowc = (pb + 1) * TROW + 1 + laneRow;   // center tile pos

    float acc[3][6][4];      // g=0..2 (x1 planes), 6 n-tiles
    float accB[4][4];        // g=3 (x0), nt=0..3 (t-class cols are zero)
    #pragma unroll
    for (int g = 0; g < 3; g++)
        #pragma unroll
        for (int t = 0; t < 6; t++)
            #pragma unroll
            for (int i = 0; i < 4; i++) acc[g][t][i] = 0.f;
    #pragma unroll
    for (int t = 0; t < 4; t++)
        #pragma unroll
        for (int i = 0; i < 4; i++) accB[t][i] = 0.f;

    const int tapoff[5] = {0, -TROW, TROW, -1, 1};   // center, x-1, x+1, y-1, y+1
    #pragma unroll
    for (int tap = 0; tap < 5; tap++) {
        const int rowb = (rowc + tapoff[tap]) * (TPH * 2) + cOffB;
        uint32_t a[4][4];                    // a[0..2]: x1 planes, a[3]: x0
        #pragma unroll
        for (int g = 0; g < 3; g++) ldsm_x4(a[g], tbase + (uint32_t)(rowb + ((1 + g) << 5)));
        ldsm_x4(a[3], tbase + (uint32_t)rowb);

        const uint32_t* bp = g_Bfrag + tap * 384 + lane;
        #pragma unroll
        for (int t = 0; t < 6; t++) {
            uint32_t B0[2];
            B0[0] = __ldg(bp + t * 64);
            B0[1] = __ldg(bp + t * 64 + 32);
            #pragma unroll
            for (int g = 0; g < 3; g++) mma_f16(acc[g][t], a[g], B0);
        }
        #pragma unroll
        for (int t = 0; t < 4; t++) {
            uint32_t B1[2];
            B1[0] = __ldg(bp + 1920 + t * 64);
            B1[1] = __ldg(bp + 1920 + t * 64 + 32);
            mma_f16(accB[t], a[3], B1);
        }
    }

    // ---- register epilogue: lane owns y-cols (lane>>2)+8sel of row pb;
    //      d values 8h + 2(lane&3) + e for h,e in {0,1}. ----
    const int m  = lane & 3;
    const int gx = xb * 8 + pb;
    #pragma unroll
    for (int sel = 0; sel < 2; sel++) {
        const int c = (lane >> 2) + 8 * sel;
        const int gy = yb * 16 + c;
        const size_t q = ((size_t)n * 128 + gx) * 128 + gy;
        const float* sp = sSpin + pb * 48 + c * 3;
        const float s0 = sp[1];
        const float s1 = sp[2];
        const float s2 = sp[0];
        float* op = out + q * 64;

        #pragma unroll
        for (int h = 0; h < 2; h++) {        // d-half: nt parity
            float o0[2], o1[2][3];
            #pragma unroll
            for (int e = 0; e < 2; e++) {
                const int i = 2 * sel + e;
                const float a0 = accB[h][i];
                const float bv = accB[2 + h][i];
                const float h0 = acc[0][h][i],     h1 = acc[1][h][i],     h2 = acc[2][h][i];
                const float a10 = acc[0][2 + h][i], a11 = acc[1][2 + h][i], a12 = acc[2][2 + h][i];
                const float t0 = acc[0][4 + h][i], t1 = acc[1][4 + h][i], t2 = acc[2][4 + h][i];
                o0[e] = a0 + h0 * s0 + h1 * s1 + h2 * s2;
                o1[e][0] = fmaf(bv, s0, a10) + (t1 * s2 - t2 * s1);
                o1[e][1] = fmaf(bv, s1, a11) + (t2 * s0 - t0 * s2);
                o1[e][2] = fmaf(bv, s2, a12) + (t0 * s1 - t1 * s0);
            }
            *(float2*)(op + 8 * h + 2 * m) = make_float2(o0[0], o0[1]);
            float* o1p = op + 16 + 24 * h + 6 * m;
            *(float2*)(o1p + 0) = make_float2(o1[0][0], o1[0][1]);
            *(float2*)(o1p + 2) = make_float2(o1[0][2], o1[1][0]);
            *(float2*)(o1p + 4) = make_float2(o1[1][1], o1[1][2]);
        }
    }
}

// ---------------------------------------------------------------------------
extern "C" void kernel_launch(void* const* d_in, const int* in_sizes, int n_in,
                              void* d_out, int out_size) {
    const float* feat = (const float*)d_in[0];
    const float* spin = (const float*)d_in[1];
    const float* w000 = (const float*)d_in[2];
    const float* w011 = (const float*)d_in[3];
    const float* w101 = (const float*)d_in[4];
    const float* w110 = (const float*)d_in[5];
    const float* w111 = (const float*)d_in[6];
    float* out = (float*)d_out;

    (void)in_sizes; (void)n_in; (void)out_size;

    cudaFuncSetAttribute(spinconv_kernel,
                         cudaFuncAttributeMaxDynamicSharedMemorySize, SMEM_BYTES);

    prep_weights<<<(NWFRAG + 255) / 256, 256>>>(w000, w011, w101, w110, w111);
    spinconv_kernel<<<8 * 16 * 8, 256, SMEM_BYTES>>>(feat, spin, out);
}